// round 1
// baseline (speedup 1.0000x reference)
#include <cuda_runtime.h>
#include <math_constants.h>

#define N_NODES 50000
#define N_EDGES 800000
#define D 64
#define DH 8
#define NSEG (N_NODES * DH)

// Device scratch (no cudaMalloc allowed)
__device__ float g_q[N_NODES * D];
__device__ float g_k[N_NODES * D];
__device__ float g_m[NSEG];
__device__ float g_s[NSEG];

// ---------------------------------------------------------------------------
// init: m = -inf, s = 0
// ---------------------------------------------------------------------------
__global__ void init_seg_kernel() {
    int i = blockIdx.x * blockDim.x + threadIdx.x;
    if (i < NSEG) {
        g_m[i] = -CUDART_INF_F;
        g_s[i] = 0.0f;
    }
}

// ---------------------------------------------------------------------------
// Fused QKV GEMM: x[N,64] @ {Wq,Wk,Wv}[64,64] + bias
// q,k -> device scratch; v -> d_out region directly.
// Block: 256 threads handles 64 nodes. Thread = (colpair c, noderow nr):
//   cols {2c,2c+1}, nodes nr + 8*j, j=0..7.
// ---------------------------------------------------------------------------
__global__ __launch_bounds__(256) void qkv_gemm_kernel(
    const float* __restrict__ x,
    const float* __restrict__ Wq, const float* __restrict__ bq,
    const float* __restrict__ Wk, const float* __restrict__ bk,
    const float* __restrict__ Wv, const float* __restrict__ bv,
    float* __restrict__ vout)
{
    __shared__ float sW[3 * D * D];      // Wq | Wk | Wv
    __shared__ float sx[64][D + 1];      // 64 nodes x 64 feats (padded)
    __shared__ float sb[3][D];

    const int tid = threadIdx.x;
    const int n0 = blockIdx.x * 64;

    // Load weights (coalesced)
    for (int i = tid; i < D * D; i += 256) {
        sW[i]            = Wq[i];
        sW[D * D + i]    = Wk[i];
        sW[2 * D * D + i]= Wv[i];
    }
    // Load x tile
    for (int idx = tid; idx < 64 * D; idx += 256) {
        int node = idx >> 6;
        int col  = idx & 63;
        int gn = n0 + node;
        sx[node][col] = (gn < N_NODES) ? x[gn * D + col] : 0.0f;
    }
    if (tid < D) {
        sb[0][tid] = bq[tid];
        sb[1][tid] = bk[tid];
        sb[2][tid] = bv[tid];
    }
    __syncthreads();

    const int c  = (tid & 31) * 2;  // output column pair
    const int nr = tid >> 5;        // node row 0..7

    float2 aq[8], ak[8], av[8];
#pragma unroll
    for (int j = 0; j < 8; j++) {
        aq[j] = make_float2(0.f, 0.f);
        ak[j] = make_float2(0.f, 0.f);
        av[j] = make_float2(0.f, 0.f);
    }

#pragma unroll 4
    for (int i = 0; i < D; i++) {
        float2 wq = *(const float2*)&sW[i * D + c];
        float2 wk = *(const float2*)&sW[D * D + i * D + c];
        float2 wv = *(const float2*)&sW[2 * D * D + i * D + c];
#pragma unroll
        for (int j = 0; j < 8; j++) {
            float xv = sx[nr + j * 8][i];
            aq[j].x += xv * wq.x; aq[j].y += xv * wq.y;
            ak[j].x += xv * wk.x; ak[j].y += xv * wk.y;
            av[j].x += xv * wv.x; av[j].y += xv * wv.y;
        }
    }

    float2 bq2 = *(const float2*)&sb[0][c];
    float2 bk2 = *(const float2*)&sb[1][c];
    float2 bv2 = *(const float2*)&sb[2][c];

#pragma unroll
    for (int j = 0; j < 8; j++) {
        int node = n0 + nr + j * 8;
        if (node < N_NODES) {
            float2 q2 = make_float2(aq[j].x + bq2.x, aq[j].y + bq2.y);
            float2 k2 = make_float2(ak[j].x + bk2.x, ak[j].y + bk2.y);
            float2 v2 = make_float2(av[j].x + bv2.x, av[j].y + bv2.y);
            *(float2*)&g_q[node * D + c] = q2;
            *(float2*)&g_k[node * D + c] = k2;
            *(float2*)&vout[node * D + c] = v2;
        }
    }
}

// ---------------------------------------------------------------------------
// Float atomic max via int-bits trick (exact, order independent)
// ---------------------------------------------------------------------------
__device__ __forceinline__ void atomicMaxF(float* addr, float val) {
    if (val >= 0.0f)
        atomicMax((int*)addr, __float_as_int(val));
    else
        atomicMin((unsigned int*)addr, __float_as_uint(val));
}

// ---------------------------------------------------------------------------
// Pass A: per-edge logits. One thread per edge.
// prods[e][d] = (1/sqrt(8)) * sum_h q[src][h*8+d] * k[dst][h*8+d]
// Also atomicMax into g_m[dst*8+d].
// ---------------------------------------------------------------------------
__global__ __launch_bounds__(128) void edge_logits_kernel(
    const int* __restrict__ edge, float* __restrict__ prods)
{
    int e = blockIdx.x * blockDim.x + threadIdx.x;
    if (e >= N_EDGES) return;
    int src = edge[e];
    int dst = edge[N_EDGES + e];

    const float4* qr = (const float4*)(g_q + src * D);
    const float4* kr = (const float4*)(g_k + dst * D);

    float a0 = 0.f, a1 = 0.f, a2 = 0.f, a3 = 0.f;
    float a4 = 0.f, a5 = 0.f, a6 = 0.f, a7 = 0.f;
#pragma unroll
    for (int h = 0; h < 8; h++) {
        float4 qa = qr[h * 2];
        float4 qb = qr[h * 2 + 1];
        float4 ka = kr[h * 2];
        float4 kb = kr[h * 2 + 1];
        a0 += qa.x * ka.x; a1 += qa.y * ka.y;
        a2 += qa.z * ka.z; a3 += qa.w * ka.w;
        a4 += qb.x * kb.x; a5 += qb.y * kb.y;
        a6 += qb.z * kb.z; a7 += qb.w * kb.w;
    }
    const float inv = 0.35355339059327373f;  // 1/sqrt(8)
    a0 *= inv; a1 *= inv; a2 *= inv; a3 *= inv;
    a4 *= inv; a5 *= inv; a6 *= inv; a7 *= inv;

    float4* po = (float4*)(prods + e * 8);
    po[0] = make_float4(a0, a1, a2, a3);
    po[1] = make_float4(a4, a5, a6, a7);

    float* mrow = g_m + dst * 8;
    atomicMaxF(mrow + 0, a0); atomicMaxF(mrow + 1, a1);
    atomicMaxF(mrow + 2, a2); atomicMaxF(mrow + 3, a3);
    atomicMaxF(mrow + 4, a4); atomicMaxF(mrow + 5, a5);
    atomicMaxF(mrow + 6, a6); atomicMaxF(mrow + 7, a7);
}

// ---------------------------------------------------------------------------
// Pass B: exp(p - m[seg]); store numerator into attention region; atomicAdd s.
// One thread per (edge, d).
// ---------------------------------------------------------------------------
__global__ __launch_bounds__(256) void edge_exp_kernel(
    const int* __restrict__ edge, const float* __restrict__ prods,
    float* __restrict__ att)
{
    int idx = blockIdx.x * blockDim.x + threadIdx.x;
    if (idx >= N_EDGES * DH) return;
    int e = idx >> 3;
    int d = idx & 7;
    int dst = edge[N_EDGES + e];
    float p = prods[idx];
    float m = g_m[dst * 8 + d];
    float ev = __expf(p - m);
    att[idx] = ev;
    atomicAdd(&g_s[dst * 8 + d], ev);
}

// ---------------------------------------------------------------------------
// s -> 1/(s + 1e-16)
// ---------------------------------------------------------------------------
__global__ void recip_kernel() {
    int i = blockIdx.x * blockDim.x + threadIdx.x;
    if (i < NSEG) {
        g_s[i] = 1.0f / (g_s[i] + 1e-16f);
    }
}

// ---------------------------------------------------------------------------
// Pass C: att *= rcp_s[seg]
// ---------------------------------------------------------------------------
__global__ __launch_bounds__(256) void edge_scale_kernel(
    const int* __restrict__ edge, float* __restrict__ att)
{
    int idx = blockIdx.x * blockDim.x + threadIdx.x;
    if (idx >= N_EDGES * DH) return;
    int e = idx >> 3;
    int d = idx & 7;
    int dst = edge[N_EDGES + e];
    att[idx] = att[idx] * g_s[dst * 8 + d];
}

// ---------------------------------------------------------------------------
// kernel_launch
// Inputs (metadata order): x, Wq, bq, Wk, bk, Wv, bv, edge
// Output: attention [E,8] | v [N,8,8] | prods [E,8]  (float32)
// ---------------------------------------------------------------------------
extern "C" void kernel_launch(void* const* d_in, const int* in_sizes, int n_in,
                              void* d_out, int out_size) {
    const float* x  = (const float*)d_in[0];
    const float* Wq = (const float*)d_in[1];
    const float* bq = (const float*)d_in[2];
    const float* Wk = (const float*)d_in[3];
    const float* bk = (const float*)d_in[4];
    const float* Wv = (const float*)d_in[5];
    const float* bv = (const float*)d_in[6];
    const int*   edge = (const int*)d_in[7];

    float* out   = (float*)d_out;
    float* att   = out;                          // E*8
    float* vout  = out + (size_t)N_EDGES * 8;    // N*64
    float* prods = vout + (size_t)N_NODES * 64;  // E*8

    init_seg_kernel<<<(NSEG + 255) / 256, 256>>>();
    qkv_gemm_kernel<<<(N_NODES + 63) / 64, 256>>>(x, Wq, bq, Wk, bk, Wv, bv, vout);
    edge_logits_kernel<<<(N_EDGES + 127) / 128, 128>>>(edge, prods);
    edge_exp_kernel<<<(N_EDGES * DH + 255) / 256, 256>>>(edge, prods, att);
    recip_kernel<<<(NSEG + 255) / 256, 256>>>();
    edge_scale_kernel<<<(N_EDGES * DH + 255) / 256, 256>>>(edge, att);
}

// round 2
// speedup vs baseline: 1.1902x; 1.1902x over previous
#include <cuda_runtime.h>
#include <math_constants.h>

#define N_NODES 50000
#define N_EDGES 800000
#define D 64
#define DH 8
#define NSEG (N_NODES * DH)

// Device scratch (no cudaMalloc allowed)
__device__ float g_q[N_NODES * D];
__device__ float g_k[N_NODES * D];
__device__ float g_s[NSEG];

// ---------------------------------------------------------------------------
// init: s = 0
// ---------------------------------------------------------------------------
__global__ void init_seg_kernel() {
    int i = blockIdx.x * blockDim.x + threadIdx.x;
    if (i < NSEG) {
        g_s[i] = 0.0f;
    }
}

// ---------------------------------------------------------------------------
// Fused QKV GEMM: x[N,64] @ {Wq,Wk,Wv}[64,64] + bias
// q,k -> device scratch; v -> d_out region directly.
// ---------------------------------------------------------------------------
__global__ __launch_bounds__(256) void qkv_gemm_kernel(
    const float* __restrict__ x,
    const float* __restrict__ Wq, const float* __restrict__ bq,
    const float* __restrict__ Wk, const float* __restrict__ bk,
    const float* __restrict__ Wv, const float* __restrict__ bv,
    float* __restrict__ vout)
{
    __shared__ float sW[3 * D * D];      // Wq | Wk | Wv
    __shared__ float sx[64][D + 1];      // 64 nodes x 64 feats (padded)
    __shared__ float sb[3][D];

    const int tid = threadIdx.x;
    const int n0 = blockIdx.x * 64;

    for (int i = tid; i < D * D; i += 256) {
        sW[i]             = Wq[i];
        sW[D * D + i]     = Wk[i];
        sW[2 * D * D + i] = Wv[i];
    }
    for (int idx = tid; idx < 64 * D; idx += 256) {
        int node = idx >> 6;
        int col  = idx & 63;
        int gn = n0 + node;
        sx[node][col] = (gn < N_NODES) ? x[gn * D + col] : 0.0f;
    }
    if (tid < D) {
        sb[0][tid] = bq[tid];
        sb[1][tid] = bk[tid];
        sb[2][tid] = bv[tid];
    }
    __syncthreads();

    const int c  = (tid & 31) * 2;  // output column pair
    const int nr = tid >> 5;        // node row 0..7

    float2 aq[8], ak[8], av[8];
#pragma unroll
    for (int j = 0; j < 8; j++) {
        aq[j] = make_float2(0.f, 0.f);
        ak[j] = make_float2(0.f, 0.f);
        av[j] = make_float2(0.f, 0.f);
    }

#pragma unroll 4
    for (int i = 0; i < D; i++) {
        float2 wq = *(const float2*)&sW[i * D + c];
        float2 wk = *(const float2*)&sW[D * D + i * D + c];
        float2 wv = *(const float2*)&sW[2 * D * D + i * D + c];
#pragma unroll
        for (int j = 0; j < 8; j++) {
            float xv = sx[nr + j * 8][i];
            aq[j].x += xv * wq.x; aq[j].y += xv * wq.y;
            ak[j].x += xv * wk.x; ak[j].y += xv * wk.y;
            av[j].x += xv * wv.x; av[j].y += xv * wv.y;
        }
    }

    float2 bq2 = *(const float2*)&sb[0][c];
    float2 bk2 = *(const float2*)&sb[1][c];
    float2 bv2 = *(const float2*)&sb[2][c];

#pragma unroll
    for (int j = 0; j < 8; j++) {
        int node = n0 + nr + j * 8;
        if (node < N_NODES) {
            float2 q2 = make_float2(aq[j].x + bq2.x, aq[j].y + bq2.y);
            float2 k2 = make_float2(ak[j].x + bk2.x, ak[j].y + bk2.y);
            float2 v2 = make_float2(av[j].x + bv2.x, av[j].y + bv2.y);
            *(float2*)&g_q[node * D + c] = q2;
            *(float2*)&g_k[node * D + c] = k2;
            *(float2*)&vout[node * D + c] = v2;
        }
    }
}

// ---------------------------------------------------------------------------
// Fused edge pass: logits + exp + vector-atomic segment sum.
// prods[e][d] = (1/sqrt(8)) * sum_h q[src][h*8+d] * k[dst][h*8+d]
// att[e][d]   = exp(prods[e][d])            (numerator; no max shift needed:
//               |p| <~ 6 so exp is fp32-safe; ratio is mathematically equal)
// g_s[dst*8+d] += att[e][d]  via red.global.add.v4.f32 (2 per edge)
// ---------------------------------------------------------------------------
__global__ __launch_bounds__(256) void edge_fused_kernel(
    const int* __restrict__ edge, float* __restrict__ prods,
    float* __restrict__ att)
{
    int e = blockIdx.x * blockDim.x + threadIdx.x;
    if (e >= N_EDGES) return;
    int src = edge[e];
    int dst = edge[N_EDGES + e];

    const float4* qr = (const float4*)(g_q + src * D);
    const float4* kr = (const float4*)(g_k + dst * D);

    float a0 = 0.f, a1 = 0.f, a2 = 0.f, a3 = 0.f;
    float a4 = 0.f, a5 = 0.f, a6 = 0.f, a7 = 0.f;
#pragma unroll
    for (int h = 0; h < 8; h++) {
        float4 qa = qr[h * 2];
        float4 qb = qr[h * 2 + 1];
        float4 ka = kr[h * 2];
        float4 kb = kr[h * 2 + 1];
        a0 += qa.x * ka.x; a1 += qa.y * ka.y;
        a2 += qa.z * ka.z; a3 += qa.w * ka.w;
        a4 += qb.x * kb.x; a5 += qb.y * kb.y;
        a6 += qb.z * kb.z; a7 += qb.w * kb.w;
    }
    const float inv = 0.35355339059327373f;  // 1/sqrt(8)
    a0 *= inv; a1 *= inv; a2 *= inv; a3 *= inv;
    a4 *= inv; a5 *= inv; a6 *= inv; a7 *= inv;

    float4* po = (float4*)(prods + e * 8);
    po[0] = make_float4(a0, a1, a2, a3);
    po[1] = make_float4(a4, a5, a6, a7);

    float e0 = __expf(a0), e1 = __expf(a1), e2 = __expf(a2), e3 = __expf(a3);
    float e4 = __expf(a4), e5 = __expf(a5), e6 = __expf(a6), e7 = __expf(a7);

    float4* ao = (float4*)(att + e * 8);
    ao[0] = make_float4(e0, e1, e2, e3);
    ao[1] = make_float4(e4, e5, e6, e7);

    float* srow = g_s + dst * 8;
    asm volatile("red.global.add.v4.f32 [%0], {%1, %2, %3, %4};"
                 :: "l"(srow), "f"(e0), "f"(e1), "f"(e2), "f"(e3) : "memory");
    asm volatile("red.global.add.v4.f32 [%0], {%1, %2, %3, %4};"
                 :: "l"(srow + 4), "f"(e4), "f"(e5), "f"(e6), "f"(e7) : "memory");
}

// ---------------------------------------------------------------------------
// s -> 1/(s + 1e-16)
// ---------------------------------------------------------------------------
__global__ void recip_kernel() {
    int i = blockIdx.x * blockDim.x + threadIdx.x;
    if (i < NSEG) {
        g_s[i] = 1.0f / (g_s[i] + 1e-16f);
    }
}

// ---------------------------------------------------------------------------
// Pass C: att *= rcp_s[seg], one thread per edge, float4 vectorized.
// ---------------------------------------------------------------------------
__global__ __launch_bounds__(256) void edge_scale_kernel(
    const int* __restrict__ edge, float* __restrict__ att)
{
    int e = blockIdx.x * blockDim.x + threadIdx.x;
    if (e >= N_EDGES) return;
    int dst = edge[N_EDGES + e];

    const float4* sr = (const float4*)(g_s + dst * 8);
    float4 s0 = sr[0];
    float4 s1 = sr[1];

    float4* ar = (float4*)(att + e * 8);
    float4 v0 = ar[0];
    float4 v1 = ar[1];
    v0.x *= s0.x; v0.y *= s0.y; v0.z *= s0.z; v0.w *= s0.w;
    v1.x *= s1.x; v1.y *= s1.y; v1.z *= s1.z; v1.w *= s1.w;
    ar[0] = v0;
    ar[1] = v1;
}

// ---------------------------------------------------------------------------
// kernel_launch
// Inputs (metadata order): x, Wq, bq, Wk, bk, Wv, bv, edge
// Output: attention [E,8] | v [N,8,8] | prods [E,8]  (float32)
// ---------------------------------------------------------------------------
extern "C" void kernel_launch(void* const* d_in, const int* in_sizes, int n_in,
                              void* d_out, int out_size) {
    const float* x  = (const float*)d_in[0];
    const float* Wq = (const float*)d_in[1];
    const float* bq = (const float*)d_in[2];
    const float* Wk = (const float*)d_in[3];
    const float* bk = (const float*)d_in[4];
    const float* Wv = (const float*)d_in[5];
    const float* bv = (const float*)d_in[6];
    const int*   edge = (const int*)d_in[7];

    float* out   = (float*)d_out;
    float* att   = out;                          // E*8
    float* vout  = out + (size_t)N_EDGES * 8;    // N*64
    float* prods = vout + (size_t)N_NODES * 64;  // E*8

    init_seg_kernel<<<(NSEG + 255) / 256, 256>>>();
    qkv_gemm_kernel<<<(N_NODES + 63) / 64, 256>>>(x, Wq, bq, Wk, bk, Wv, bv, vout);
    edge_fused_kernel<<<(N_EDGES + 255) / 256, 256>>>(edge, prods, att);
    recip_kernel<<<(NSEG + 255) / 256, 256>>>();
    edge_scale_kernel<<<(N_EDGES + 255) / 256, 256>>>(edge, att);
}

// round 3
// speedup vs baseline: 1.9924x; 1.6741x over previous
#include <cuda_runtime.h>
#include <math_constants.h>

#define N_NODES 50000
#define N_EDGES 800000
#define D 64
#define DH 8
#define NSEG (N_NODES * DH)

// Device scratch (no cudaMalloc allowed)
__device__ __align__(16) float g_q[N_NODES * D];
__device__ __align__(16) float g_k[N_NODES * D];
__device__ __align__(16) float g_s[NSEG];

// ---------------------------------------------------------------------------
// Fused QKV GEMM: x[N,64] @ {Wq,Wk,Wv}[64,64] + bias
// Also zero-inits g_s (fused; saves one launch).
// q,k -> device scratch; v -> d_out region directly.
// ---------------------------------------------------------------------------
__global__ __launch_bounds__(256) void qkv_gemm_kernel(
    const float* __restrict__ x,
    const float* __restrict__ Wq, const float* __restrict__ bq,
    const float* __restrict__ Wk, const float* __restrict__ bk,
    const float* __restrict__ Wv, const float* __restrict__ bv,
    float* __restrict__ vout)
{
    __shared__ float sW[3 * D * D];      // Wq | Wk | Wv
    __shared__ float sx[64][D + 1];      // 64 nodes x 64 feats (padded)
    __shared__ float sb[3][D];

    const int tid = threadIdx.x;
    const int n0 = blockIdx.x * 64;

    // Fused init: zero g_s (400000 floats = 200000 float2; 782*256 = 200192 thr)
    {
        int gtid = blockIdx.x * 256 + tid;
        if (gtid < NSEG / 2) {
            ((float2*)g_s)[gtid] = make_float2(0.f, 0.f);
        }
    }

    for (int i = tid; i < D * D; i += 256) {
        sW[i]             = Wq[i];
        sW[D * D + i]     = Wk[i];
        sW[2 * D * D + i] = Wv[i];
    }
    for (int idx = tid; idx < 64 * D; idx += 256) {
        int node = idx >> 6;
        int col  = idx & 63;
        int gn = n0 + node;
        sx[node][col] = (gn < N_NODES) ? x[gn * D + col] : 0.0f;
    }
    if (tid < D) {
        sb[0][tid] = bq[tid];
        sb[1][tid] = bk[tid];
        sb[2][tid] = bv[tid];
    }
    __syncthreads();

    const int c  = (tid & 31) * 2;  // output column pair
    const int nr = tid >> 5;        // node row 0..7

    float2 aq[8], ak[8], av[8];
#pragma unroll
    for (int j = 0; j < 8; j++) {
        aq[j] = make_float2(0.f, 0.f);
        ak[j] = make_float2(0.f, 0.f);
        av[j] = make_float2(0.f, 0.f);
    }

#pragma unroll 4
    for (int i = 0; i < D; i++) {
        float2 wq = *(const float2*)&sW[i * D + c];
        float2 wk = *(const float2*)&sW[D * D + i * D + c];
        float2 wv = *(const float2*)&sW[2 * D * D + i * D + c];
#pragma unroll
        for (int j = 0; j < 8; j++) {
            float xv = sx[nr + j * 8][i];
            aq[j].x += xv * wq.x; aq[j].y += xv * wq.y;
            ak[j].x += xv * wk.x; ak[j].y += xv * wk.y;
            av[j].x += xv * wv.x; av[j].y += xv * wv.y;
        }
    }

    float2 bq2 = *(const float2*)&sb[0][c];
    float2 bk2 = *(const float2*)&sb[1][c];
    float2 bv2 = *(const float2*)&sb[2][c];

#pragma unroll
    for (int j = 0; j < 8; j++) {
        int node = n0 + nr + j * 8;
        if (node < N_NODES) {
            float2 q2 = make_float2(aq[j].x + bq2.x, aq[j].y + bq2.y);
            float2 k2 = make_float2(ak[j].x + bk2.x, ak[j].y + bk2.y);
            float2 v2 = make_float2(av[j].x + bv2.x, av[j].y + bv2.y);
            *(float2*)&g_q[node * D + c] = q2;
            *(float2*)&g_k[node * D + c] = k2;
            *(float2*)&vout[node * D + c] = v2;
        }
    }
}

// ---------------------------------------------------------------------------
// Warp-cooperative fused edge pass: logits + exp + vec4-atomic segment sum.
// 8 lanes per edge, 4 edges per warp. All row gathers are fully coalesced
// (lane d loads float4 chunks d and d+8 of the 256B row).
// Requires N_EDGES % 4 == 0 (800000/4 = 200000 warps = 25000 blocks exact).
// ---------------------------------------------------------------------------
__global__ __launch_bounds__(256) void edge_fused_kernel(
    const int* __restrict__ edge, float* __restrict__ prods,
    float* __restrict__ att)
{
    const int lane = threadIdx.x & 31;
    const int warp = (blockIdx.x * 256 + threadIdx.x) >> 5;
    const int e0   = warp * 4;       // first edge of this warp
    const int sub  = lane >> 3;      // edge slot 0..3
    const int d    = lane & 7;       // lane within edge group
    const int e    = e0 + sub;

    const int src = edge[e];
    const int dst = edge[N_EDGES + e];

    const float4* q4 = (const float4*)(g_q + src * D);
    const float4* k4 = (const float4*)(g_k + dst * D);

    // Lane d holds row floats [d*4, d*4+4) and [32+d*4, 32+d*4+4):
    // i.e. heads h=d>>1 and h=4+(d>>1), dims dd = (d&1)*4 + {0..3}.
    float4 qa = q4[d];
    float4 qb = q4[d + 8];
    float4 ka = k4[d];
    float4 kb = k4[d + 8];

    // partial per-dd products, summed over this lane's two heads
    float w0 = qa.x * ka.x + qb.x * kb.x;
    float w1 = qa.y * ka.y + qb.y * kb.y;
    float w2 = qa.z * ka.z + qb.z * kb.z;
    float w3 = qa.w * ka.w + qb.w * kb.w;

    const unsigned FULL = 0xffffffffu;

    // transpose-reduce over 4 lanes (bits 1,2 of lane) sharing parity bit0
    // step 1: xor 4 — keep low pair if bit2==0, high pair otherwise
    {
        float t0 = (lane & 4) ? w0 : w2;
        float t1 = (lane & 4) ? w1 : w3;
        float u0 = __shfl_xor_sync(FULL, t0, 4);
        float u1 = __shfl_xor_sync(FULL, t1, 4);
        w0 = ((lane & 4) ? w2 : w0) + u0;
        w1 = ((lane & 4) ? w3 : w1) + u1;
    }
    // step 2: xor 2
    float p;
    {
        float t2 = (lane & 2) ? w0 : w1;
        float u2 = __shfl_xor_sync(FULL, t2, 2);
        p = ((lane & 2) ? w1 : w0) + u2;
    }
    // Now lane d holds dd(d) = ((d&1)<<2) | ((d&4)>>1) | ((d&2)>>1).
    // Permute so lane d holds dd == d: source lane s has
    // bit0(s)=bit2(d), bit1(s)=bit0(d), bit2(s)=bit1(d).
    {
        int srcl = (sub << 3) | ((d >> 2) & 1) | ((d & 1) << 1) | ((d & 2) << 1);
        p = __shfl_sync(FULL, p, srcl);
    }

    p *= 0.35355339059327373f;  // 1/sqrt(8)

    // coalesced stores: offset e*8 + d == e0*8 + lane
    size_t off = (size_t)e0 * 8 + lane;
    prods[off] = p;
    float ev = __expf(p);
    att[off] = ev;

    // gather 4 lanes' ev into vec4 atomic (lanes d==0 and d==4 issue)
    float p1 = __shfl_down_sync(FULL, ev, 1);
    float p2 = __shfl_down_sync(FULL, ev, 2);
    float p3 = __shfl_down_sync(FULL, ev, 3);
    if ((lane & 3) == 0) {
        float* srow = g_s + dst * 8 + (lane & 4);
        asm volatile("red.global.add.v4.f32 [%0], {%1, %2, %3, %4};"
                     :: "l"(srow), "f"(ev), "f"(p1), "f"(p2), "f"(p3) : "memory");
    }
}

// ---------------------------------------------------------------------------
// s -> 1/(s + 1e-16)
// ---------------------------------------------------------------------------
__global__ void recip_kernel() {
    int i = blockIdx.x * blockDim.x + threadIdx.x;
    if (i < NSEG / 4) {
        float4 v = ((const float4*)g_s)[i];
        v.x = 1.0f / (v.x + 1e-16f);
        v.y = 1.0f / (v.y + 1e-16f);
        v.z = 1.0f / (v.z + 1e-16f);
        v.w = 1.0f / (v.w + 1e-16f);
        ((float4*)g_s)[i] = v;
    }
}

// ---------------------------------------------------------------------------
// Pass C: att *= rcp_s[seg], one thread per edge, float4 vectorized.
// ---------------------------------------------------------------------------
__global__ __launch_bounds__(256) void edge_scale_kernel(
    const int* __restrict__ edge, float* __restrict__ att)
{
    int e = blockIdx.x * blockDim.x + threadIdx.x;
    if (e >= N_EDGES) return;
    int dst = edge[N_EDGES + e];

    const float4* sr = (const float4*)(g_s + dst * 8);
    float4 s0 = sr[0];
    float4 s1 = sr[1];

    float4* ar = (float4*)(att + (size_t)e * 8);
    float4 v0 = ar[0];
    float4 v1 = ar[1];
    v0.x *= s0.x; v0.y *= s0.y; v0.z *= s0.z; v0.w *= s0.w;
    v1.x *= s1.x; v1.y *= s1.y; v1.z *= s1.z; v1.w *= s1.w;
    ar[0] = v0;
    ar[1] = v1;
}

// ---------------------------------------------------------------------------
// kernel_launch
// Inputs (metadata order): x, Wq, bq, Wk, bk, Wv, bv, edge
// Output: attention [E,8] | v [N,8,8] | prods [E,8]  (float32)
// ---------------------------------------------------------------------------
extern "C" void kernel_launch(void* const* d_in, const int* in_sizes, int n_in,
                              void* d_out, int out_size) {
    const float* x  = (const float*)d_in[0];
    const float* Wq = (const float*)d_in[1];
    const float* bq = (const float*)d_in[2];
    const float* Wk = (const float*)d_in[3];
    const float* bk = (const float*)d_in[4];
    const float* Wv = (const float*)d_in[5];
    const float* bv = (const float*)d_in[6];
    const int*   edge = (const int*)d_in[7];

    float* out   = (float*)d_out;
    float* att   = out;                          // E*8
    float* vout  = out + (size_t)N_EDGES * 8;    // N*64
    float* prods = vout + (size_t)N_NODES * 64;  // E*8

    qkv_gemm_kernel<<<(N_NODES + 63) / 64, 256>>>(x, Wq, bq, Wk, bk, Wv, bv, vout);
    edge_fused_kernel<<<N_EDGES / 32, 256>>>(edge, prods, att);
    recip_kernel<<<(NSEG / 4 + 255) / 256, 256>>>();
    edge_scale_kernel<<<(N_EDGES + 255) / 256, 256>>>(edge, att);
}